// round 16
// baseline (speedup 1.0000x reference)
#include <cuda_runtime.h>
#include <cuda_fp16.h>
#include <math.h>
#include <stdint.h>

// Problem constants
#define BATCH   2
#define N_SEQ   2048
#define EMB     512
#define NHEAD   8
#define HD      64
#define M_ROWS  (BATCH * N_SEQ)   // 4096

// ---------------- scratch ----------------------------------------------------
__device__ __half g_xh[M_ROWS * EMB];
__device__ __half g_wqh[EMB * EMB];
__device__ __half g_wkh[EMB * EMB];
__device__ __half g_Qh[M_ROWS * EMB];
__device__ __half g_Kh[M_ROWS * EMB];
__device__ float  g_xpart[BATCH * 16 * EMB];
__device__ float  g_bs[BATCH * 4 * EMB];
__device__ float  g_U[BATCH * NHEAD * 4 * EMB];

// ---------------- side stream for the value/output prep branch ----------------
struct SideStream {
    cudaStream_t s2;
    cudaEvent_t  evF, evJ;
    SideStream() {
        cudaStreamCreateWithFlags(&s2, cudaStreamNonBlocking);
        cudaEventCreateWithFlags(&evF, cudaEventDisableTiming);
        cudaEventCreateWithFlags(&evJ, cudaEventDisableTiming);
    }
};
static SideStream g_ss;

// ---------------- helpers ------------------------------------------------------
__device__ __forceinline__ uint32_t smem_u32(const void* p) {
    uint32_t a;
    asm("{ .reg .u64 t; cvta.to.shared.u64 t, %1; cvt.u32.u64 %0, t; }"
        : "=r"(a) : "l"(p));
    return a;
}

__device__ __forceinline__ void cp16(uint32_t dst, const void* src) {
    asm volatile("cp.async.cg.shared.global [%0], [%1], 16;"
                 :: "r"(dst), "l"(src) : "memory");
}
__device__ __forceinline__ void cp_commit() {
    asm volatile("cp.async.commit_group;" ::: "memory");
}
template <int N> __device__ __forceinline__ void cp_wait() {
    asm volatile("cp.async.wait_group %0;" :: "n"(N) : "memory");
}

__device__ __forceinline__ void mma_f16(float d[4], const uint32_t a[4],
                                        const uint32_t b0, const uint32_t b1) {
    asm volatile(
        "mma.sync.aligned.m16n8k16.row.col.f32.f16.f16.f32 "
        "{%0,%1,%2,%3}, {%4,%5,%6,%7}, {%8,%9}, {%0,%1,%2,%3};"
        : "+f"(d[0]), "+f"(d[1]), "+f"(d[2]), "+f"(d[3])
        : "r"(a[0]), "r"(a[1]), "r"(a[2]), "r"(a[3]), "r"(b0), "r"(b1));
}

__device__ __forceinline__ void ldsm_x4(uint32_t& r0, uint32_t& r1,
                                        uint32_t& r2, uint32_t& r3, uint32_t addr) {
    asm volatile("ldmatrix.sync.aligned.m8n8.x4.shared.b16 {%0,%1,%2,%3}, [%4];"
                 : "=r"(r0), "=r"(r1), "=r"(r2), "=r"(r3) : "r"(addr));
}

// ---------------- fp32 -> fp16 converts (split) ---------------------------------
#define PH_X_F4 (M_ROWS * EMB / 4)   // 524288
#define PH_W_F4 (EMB * EMB / 4)      // 65536

__global__ __launch_bounds__(256)
void prep_w(const float* __restrict__ Wq, const float* __restrict__ Wk,
            __half* __restrict__ wqh, __half* __restrict__ wkh) {
    const int total = 2 * PH_W_F4;
    for (int i = blockIdx.x * 256 + threadIdx.x; i < total; i += gridDim.x * 256) {
        const float4* src = (i < PH_W_F4) ? (const float4*)Wq : (const float4*)Wk;
        __half2* dst = (i < PH_W_F4) ? (__half2*)wqh : (__half2*)wkh;
        const int off = (i < PH_W_F4) ? i : i - PH_W_F4;
        float4 v = src[off];
        dst[off * 2]     = __floats2half2_rn(v.x, v.y);
        dst[off * 2 + 1] = __floats2half2_rn(v.z, v.w);
    }
}

__global__ __launch_bounds__(256)
void prep_x(const float* __restrict__ x, __half* __restrict__ xh) {
    for (int i = blockIdx.x * 256 + threadIdx.x; i < PH_X_F4; i += gridDim.x * 256) {
        float4 v = ((const float4*)x)[i];
        ((__half2*)xh)[i * 2]     = __floats2half2_rn(v.x, v.y);
        ((__half2*)xh)[i * 2 + 1] = __floats2half2_rn(v.z, v.w);
    }
}

// ---------------- x partial sums (side branch, reads fp32 x) -------------------
__global__ __launch_bounds__(256)
void xpart_kernel(const float* __restrict__ x, float* __restrict__ xpart) {
    __shared__ float4 stage[128];
    const int b = blockIdx.x;
    const int c = blockIdx.y;
    const int t = threadIdx.x;
    const int fc = t & 127;
    const int half = t >> 7;

    const float4* base = (const float4*)(x + ((size_t)b * N_SEQ + c * 128 + half * 64) * EMB);
    float4 s = make_float4(0.f, 0.f, 0.f, 0.f);
    #pragma unroll 8
    for (int n = 0; n < 64; n++) {
        float4 v = base[(size_t)n * (EMB / 4) + fc];
        s.x += v.x; s.y += v.y; s.z += v.z; s.w += v.w;
    }
    if (half == 1) stage[fc] = s;
    __syncthreads();
    if (half == 0) {
        float4 o = stage[fc];
        o.x += s.x; o.y += s.y; o.z += s.z; o.w += s.w;
        *(float4*)(xpart + ((size_t)b * 16 + c) * EMB + fc * 4) = o;
    }
}

// ---------------- fp16 mma.sync GEMM: Q,K = X @ W.T + b (fp16 out) -------------
// CTA tile 128x256, 16 warps (2x8), warp tile 64x32, 4-stage, ldmatrix frags.
#define GBM 128
#define GBN 256
#define BKH 64
#define SAH 72                          // padded row stride in halves
#define A_TILE_H (GBM * SAH)            // 9216 halves
#define B_TILE_H (GBN * SAH)            // 18432 halves
#define A_BYTES  (A_TILE_H * 2)         // 18432
#define STAGE_BYTES ((A_TILE_H + B_TILE_H) * 2)   // 55296
#define NSTAGE 4
#define NKIT (EMB / BKH)                // 8
#define GEMM_SMEM (STAGE_BYTES * NSTAGE)          // 221184

__global__ __launch_bounds__(512, 1)
void qk_gemm_f16(const __half* __restrict__ xh,
                 const __half* __restrict__ wqh, const float* __restrict__ bq,
                 const __half* __restrict__ wkh, const float* __restrict__ bk,
                 __half* __restrict__ Qout, __half* __restrict__ Kout) {
    extern __shared__ __half smh[];
    const int tid  = threadIdx.x;
    const int wid  = tid >> 5;
    const int lane = tid & 31;
    const int wm   = wid >> 3;
    const int wn   = wid & 7;
    const int g    = lane >> 2;
    const int tg   = lane & 3;

    const __half* W    = blockIdx.z ? wkh : wqh;
    const float*  bias = blockIdx.z ? bk  : bq;
    __half*       C    = blockIdx.z ? Kout : Qout;
    const int m0 = blockIdx.x * GBM;
    const int n0 = blockIdx.y * GBN;

    const uint32_t uS = smem_u32(smh);

    float acc[4][4][4];
    #pragma unroll
    for (int i = 0; i < 4; i++)
        #pragma unroll
        for (int j = 0; j < 4; j++)
            #pragma unroll
            for (int k = 0; k < 4; k++) acc[i][j][k] = 0.f;

    uint32_t aOff[4], bOff[2];
    {
        const int ar = (lane & 15);
        const int ac = ((lane >> 4) & 1) * 8;
        #pragma unroll
        for (int mt = 0; mt < 4; mt++)
            aOff[mt] = (uint32_t)(((wm * 64 + mt * 16 + ar) * SAH + ac) * 2);
        const int br = (lane & 7) + ((lane >> 4) & 1) * 8;
        const int bc = ((lane >> 3) & 1) * 8;
        #pragma unroll
        for (int p = 0; p < 2; p++)
            bOff[p] = (uint32_t)(A_BYTES + ((wn * 32 + p * 16 + br) * SAH + bc) * 2);
    }

    const int arow = tid >> 2;
    const int acb  = (tid & 3) * 2;
    const int brow = tid >> 1;
    const int bcb  = (tid & 1) * 4;

    auto load_stage = [&](int k0, int s) {
        const uint32_t base = uS + (uint32_t)s * STAGE_BYTES;
        #pragma unroll
        for (int i = 0; i < 2; i++) {
            const int ch = acb + i;
            cp16(base + (uint32_t)(arow * SAH + ch * 8) * 2,
                 xh + (size_t)(m0 + arow) * EMB + k0 + ch * 8);
        }
        #pragma unroll
        for (int i = 0; i < 4; i++) {
            const int ch = bcb + i;
            cp16(base + A_BYTES + (uint32_t)(brow * SAH + ch * 8) * 2,
                 W + (size_t)(n0 + brow) * EMB + k0 + ch * 8);
        }
    };

    load_stage(0, 0);          cp_commit();
    load_stage(BKH, 1);        cp_commit();
    load_stage(2 * BKH, 2);    cp_commit();

    #pragma unroll 1
    for (int c = 0; c < NKIT; c++) {
        if (c <= NKIT - 3)      { cp_wait<2>(); }
        else if (c == NKIT - 2) { cp_wait<1>(); }
        else                    { cp_wait<0>(); }
        __syncthreads();
        if (c + 3 < NKIT) {
            load_stage((c + 3) * BKH, (c + 3) & (NSTAGE - 1));
            cp_commit();
        }

        const uint32_t sBase = uS + (uint32_t)(c & (NSTAGE - 1)) * STAGE_BYTES;

        #pragma unroll
        for (int ks = 0; ks < 4; ks++) {
            const uint32_t kb = ks * 32;
            uint32_t af[4][4];
            #pragma unroll
            for (int mt = 0; mt < 4; mt++)
                ldsm_x4(af[mt][0], af[mt][1], af[mt][2], af[mt][3],
                        sBase + aOff[mt] + kb);
            uint32_t bf[2][4];
            #pragma unroll
            for (int p = 0; p < 2; p++)
                ldsm_x4(bf[p][0], bf[p][1], bf[p][2], bf[p][3],
                        sBase + bOff[p] + kb);
            #pragma unroll
            for (int mt = 0; mt < 4; mt++) {
                #pragma unroll
                for (int p = 0; p < 2; p++) {
                    mma_f16(acc[mt][p * 2],     af[mt], bf[p][0], bf[p][1]);
                    mma_f16(acc[mt][p * 2 + 1], af[mt], bf[p][2], bf[p][3]);
                }
            }
        }
    }

    // epilogue: bias add + half2 stores
    #pragma unroll
    for (int mt = 0; mt < 4; mt++) {
        const int r = m0 + wm * 64 + mt * 16 + g;
        #pragma unroll
        for (int nt = 0; nt < 4; nt++) {
            const int cn = n0 + wn * 32 + nt * 8 + tg * 2;
            const float2 bb = *(const float2*)(bias + cn);
            __half2 v0 = __floats2half2_rn(acc[mt][nt][0] + bb.x,
                                           acc[mt][nt][1] + bb.y);
            __half2 v1 = __floats2half2_rn(acc[mt][nt][2] + bb.x,
                                           acc[mt][nt][3] + bb.y);
            *(__half2*)(C + (size_t)r * EMB + cn)       = v0;
            *(__half2*)(C + (size_t)(r + 8) * EMB + cn) = v1;
        }
    }
}

// ---------------- basis: bs[b][j][row] = dot(Wv[row], vec_j) + bv*scale --------
__global__ __launch_bounds__(256)
void basis_kernel(const float* __restrict__ x, const float* __restrict__ xpart,
                  const float* __restrict__ Wv, const float* __restrict__ bv,
                  float* __restrict__ bs) {
    __shared__ float vec[4 * EMB];
    const int b = blockIdx.x;
    const int t = threadIdx.x;
    const int w = t >> 5, lane = t & 31;

    #pragma unroll
    for (int rep = 0; rep < 2; rep++) {
        const int col = t + rep * 256;
        float s = 0.f;
        #pragma unroll
        for (int r = 0; r < 16; r++)
            s += xpart[((size_t)b * 16 + r) * EMB + col];
        vec[col] = s;
    }
    #pragma unroll
    for (int j = 1; j < 4; j++) {
        float2 v = ((const float2*)(x + ((size_t)b * N_SEQ + (j - 1)) * EMB))[t];
        ((float2*)(vec + j * EMB))[t] = v;
    }
    __syncthreads();

    const int row = blockIdx.y * 8 + w;
    const float4* wr = (const float4*)(Wv + (size_t)row * EMB);
    float4 wv[4];
    #pragma unroll
    for (int i = 0; i < 4; i++) wv[i] = wr[lane + 32 * i];

    float a[4];
    #pragma unroll
    for (int j = 0; j < 4; j++) {
        const float4* vr = (const float4*)(vec + j * EMB);
        float s = 0.f;
        #pragma unroll
        for (int i = 0; i < 4; i++) {
            float4 vv = vr[lane + 32 * i];
            s += wv[i].x * vv.x + wv[i].y * vv.y + wv[i].z * vv.z + wv[i].w * vv.w;
        }
        a[j] = s;
    }
    #pragma unroll
    for (int off = 16; off; off >>= 1)
        #pragma unroll
        for (int j = 0; j < 4; j++)
            a[j] += __shfl_xor_sync(0xffffffff, a[j], off);
    if (lane < 4) {
        const int j = lane;
        const float scale = (j == 0) ? (float)N_SEQ : 1.f;
        bs[((size_t)b * 4 + j) * EMB + row] = a[j] + bv[row] * scale;
    }
}

// ---------------- U[b][h][j][eo] = sum_d Wo[eo][h*64+d] * bs[b][j][h*64+d] -----
__global__ __launch_bounds__(256)
void u_kernel(const float* __restrict__ bs, const float* __restrict__ Wo,
              float* __restrict__ U) {
    __shared__ float sWo[128 * 65];
    __shared__ float sbs[4][HD];
    const int bh = blockIdx.x;
    const int b = bh >> 3, h = bh & 7;
    const int eo0 = blockIdx.y * 128;
    const int t = threadIdx.x;

    if (t < 4 * HD) {
        const int j = t >> 6, d = t & 63;
        sbs[j][d] = bs[((size_t)b * 4 + j) * EMB + h * HD + d];
    }
    #pragma unroll
    for (int i = 0; i < 8; i++) {
        const int fi = t + 256 * i;
        const int r = fi >> 4, c4 = fi & 15;
        float4 v = *(const float4*)(Wo + (size_t)(eo0 + r) * EMB + h * HD + c4 * 4);
        float* dst = sWo + r * 65 + c4 * 4;
        dst[0] = v.x; dst[1] = v.y; dst[2] = v.z; dst[3] = v.w;
    }
    __syncthreads();

    const int eo = t & 127;
    const int jp = t >> 7;
    const float* wrow = sWo + eo * 65;
    float a0 = 0.f, a1 = 0.f;
    #pragma unroll 8
    for (int d = 0; d < HD; d++) {
        const float wv = wrow[d];
        a0 = fmaf(wv, sbs[jp * 2][d],     a0);
        a1 = fmaf(wv, sbs[jp * 2 + 1][d], a1);
    }
    U[((size_t)(b * NHEAD + h) * 4 + jp * 2)     * EMB + eo0 + eo] = a0;
    U[((size_t)(b * NHEAD + h) * 4 + jp * 2 + 1) * EMB + eo0 + eo] = a1;
}

// ---------------- fused coef + out ----------------------------------------------
__global__ __launch_bounds__(256)
void coef_out_kernel(const __half* __restrict__ Q, const __half* __restrict__ K,
                     const float* __restrict__ U, const float* __restrict__ bo,
                     float* __restrict__ out) {
    const int blk = blockIdx.x;
    const int b = blk >> 7;
    const int r0 = (blk & 127) * 16;
    const int t = threadIdx.x;
    const int h = t >> 5;
    const int lane = t & 31;

    float u0[32], u1[32];
    #pragma unroll
    for (int hj = 0; hj < 32; hj++) {
        u0[hj] = U[((size_t)b * 32 + hj) * EMB + t];
        u1[hj] = U[((size_t)b * 32 + hj) * EMB + t + 256];
    }

    __shared__ float sc[16][32];
    const size_t base = ((size_t)b * N_SEQ) * EMB + h * HD;
    #pragma unroll 2
    for (int rr = 0; rr < 16; rr++) {
        const int r = r0 + rr;
        const __half2 q2 = ((const __half2*)(Q + base + (size_t)r * EMB))[lane];
        const float2 qf = __half22float2(q2);
        float v[3];
        bool valid[3];
        #pragma unroll
        for (int c = 0; c < 3; c++) {
            const int kr = r + c - 1;
            valid[c] = (kr >= 0 && kr < N_SEQ);
            if (valid[c]) {
                const __half2 k2 = ((const __half2*)(K + base + (size_t)kr * EMB))[lane];
                const float2 kf = __half22float2(k2);
                v[c] = qf.x * kf.x + qf.y * kf.y;
            } else v[c] = 0.f;
        }
        #pragma unroll
        for (int off = 16; off; off >>= 1)
            #pragma unroll
            for (int c = 0; c < 3; c++)
                v[c] += __shfl_xor_sync(0xffffffff, v[c], off);
        float e[3];
        #pragma unroll
        for (int c = 0; c < 3; c++)
            e[c] = valid[c] ? (expf(v[c]) - 1.f) : 0.f;
        const float inv = 1.f / ((float)N_SEQ + e[0] + e[1] + e[2]);
        if (lane < 4)
            sc[rr][h * 4 + lane] = (lane == 0) ? inv : inv * e[lane - 1];
    }
    __syncthreads();

    const float bo0 = bo[t], bo1 = bo[t + 256];
    #pragma unroll 2
    for (int rr = 0; rr < 16; rr++) {
        float a0 = bo0, a1 = bo1;
        #pragma unroll
        for (int hj = 0; hj < 32; hj++) {
            const float c = sc[rr][hj];
            a0 = fmaf(c, u0[hj], a0);
            a1 = fmaf(c, u1[hj], a1);
        }
        const size_t ob = ((size_t)b * N_SEQ + r0 + rr) * EMB;
        out[ob + t]       = a0;
        out[ob + t + 256] = a1;
    }
}

// ---------------- launch ----------------------------------------------------------
extern "C" void kernel_launch(void* const* d_in, const int* in_sizes, int n_in,
                              void* d_out, int out_size) {
    const float* x  = (const float*)d_in[0];
    const float* Wq = (const float*)d_in[1];
    const float* bq = (const float*)d_in[2];
    const float* Wk = (const float*)d_in[3];
    const float* bk = (const float*)d_in[4];
    const float* Wv = (const float*)d_in[5];
    const float* bv = (const float*)d_in[6];
    const float* Wo = (const float*)d_in[7];
    const float* bo = (const float*)d_in[8];
    float* outp = (float*)d_out;

    __half *xh, *wqh, *wkh, *Qp, *Kp;
    float *xpp, *bsp, *Up;
    cudaGetSymbolAddress((void**)&xh,  g_xh);
    cudaGetSymbolAddress((void**)&wqh, g_wqh);
    cudaGetSymbolAddress((void**)&wkh, g_wkh);
    cudaGetSymbolAddress((void**)&Qp,  g_Qh);
    cudaGetSymbolAddress((void**)&Kp,  g_Kh);
    cudaGetSymbolAddress((void**)&xpp, g_xpart);
    cudaGetSymbolAddress((void**)&bsp, g_bs);
    cudaGetSymbolAddress((void**)&Up,  g_U);

    cudaFuncSetAttribute(qk_gemm_f16,
                         cudaFuncAttributeMaxDynamicSharedMemorySize, GEMM_SMEM);

    // Fork side branch immediately (depends only on raw inputs).
    cudaEventRecord(g_ss.evF, 0);
    cudaStreamWaitEvent(g_ss.s2, g_ss.evF, 0);

    // Branch A (main): W convert -> x convert -> GEMM
    prep_w<<<128, 256>>>(Wq, Wk, wqh, wkh);                       // issue #1
    prep_x<<<512, 256>>>(x, xh);                                  // issue #2
    xpart_kernel<<<dim3(BATCH, 16), 256, 0, g_ss.s2>>>(x, xpp);   // issue #3 (side)
    qk_gemm_f16<<<dim3(M_ROWS / GBM, EMB / GBN, 2), 512, GEMM_SMEM>>>(
        xh, wqh, bq, wkh, bk, Qp, Kp);                            // issue #4 (ncu slot)

    // Branch B (side): basis -> U
    basis_kernel<<<dim3(BATCH, 64), 256, 0, g_ss.s2>>>(x, xpp, Wv, bv, bsp);
    u_kernel<<<dim3(BATCH * NHEAD, 4), 256, 0, g_ss.s2>>>(bsp, Wo, Up);

    // Join, then final combine
    cudaEventRecord(g_ss.evJ, g_ss.s2);
    cudaStreamWaitEvent(0, g_ss.evJ, 0);

    coef_out_kernel<<<256, 256>>>(Qp, Kp, Up, bo, outp);
}